// round 15
// baseline (speedup 1.0000x reference)
#include <cuda_runtime.h>
#include <cuda_fp16.h>
#include <cstdint>

#define Nn 50000
#define Ee 800000
#define FIN 256
#define F1 32
#define H1 8
#define NHID 256
#define NC 47

// ---------------- scratch (device globals: allocation-free) ----------------
__device__ int    g_rowptr[Nn + 1];
__device__ int    g_cursor[Nn];
__device__ int    g_csr_dst[Ee];
__device__ int    g_bsums[64];
__device__ int    g_sflag[64];
__device__ __half g_h1h[Nn * F1];        // 3.2 MB fp16 gather array (layer 1)
__device__ float  g_el1[Nn * H1];
__device__ __half g_er1h[Nn * H1];       // 0.8 MB fp16 gather array
__device__ __half g_r1h[Nn * NHID];      // 25.6 MB fp16 hidden activations
__device__ __half g_h2ph[Nn * 48];       // 4.8 MB fp16 gather array (layer 2)
__device__ float  g_el2[Nn];
__device__ float  g_er2[Nn];

// ---------------- tf32 mma helpers ----------------
__device__ __forceinline__ uint32_t f2tf32(float f) {
    uint32_t r;
    asm("cvt.rna.tf32.f32 %0, %1;" : "=r"(r) : "f"(f));
    return r;
}

__device__ __forceinline__ void mma_tf32(float* d,
    uint32_t a0, uint32_t a1, uint32_t a2, uint32_t a3,
    uint32_t b0, uint32_t b1) {
    asm volatile(
        "mma.sync.aligned.m16n8k8.row.col.f32.tf32.tf32.f32 "
        "{%0,%1,%2,%3},{%4,%5,%6,%7},{%8,%9},{%0,%1,%2,%3};\n"
        : "+f"(d[0]), "+f"(d[1]), "+f"(d[2]), "+f"(d[3])
        : "r"(a0), "r"(a1), "r"(a2), "r"(a3), "r"(b0), "r"(b1));
}

// fp16 mma m16n8k16, fp32 accumulate
__device__ __forceinline__ void mma_f16(float* d,
    uint32_t a0, uint32_t a1, uint32_t a2, uint32_t a3,
    uint32_t b0, uint32_t b1) {
    asm volatile(
        "mma.sync.aligned.m16n8k16.row.col.f32.f16.f16.f32 "
        "{%0,%1,%2,%3},{%4,%5,%6,%7},{%8,%9},{%0,%1,%2,%3};\n"
        : "+f"(d[0]), "+f"(d[1]), "+f"(d[2]), "+f"(d[3])
        : "r"(a0), "r"(a1), "r"(a2), "r"(a3), "r"(b0), "r"(b1));
}

__device__ __forceinline__ void ldmatrix_x4_trans(uint32_t& r0, uint32_t& r1,
                                                  uint32_t& r2, uint32_t& r3,
                                                  uint32_t addr) {
    asm volatile("ldmatrix.sync.aligned.m8n8.x4.trans.shared.b16 {%0,%1,%2,%3}, [%4];"
        : "=r"(r0), "=r"(r1), "=r"(r2), "=r"(r3) : "r"(addr));
}

__device__ __forceinline__ float4 h4_to_f4(uint2 r) {
    __half2 p0 = *(__half2*)&r.x, p1 = *(__half2*)&r.y;
    return make_float4(__low2float(p0), __high2float(p0),
                       __low2float(p1), __high2float(p1));
}

// ---------------- zero / sentinel init ----------------
__global__ void k_zero() {
    int i = blockIdx.x * 256 + threadIdx.x;
    if (i < Nn + 1) g_rowptr[i] = 0;
    if (i < 64) { g_bsums[i] = -1; g_sflag[i] = 0; }
}

// ---------------- GEMM1 (tf32, fused: edge count + B prep + MMA) ----------------
#define S1P 100
__global__ void __launch_bounds__(256) k_gemm1(const float* __restrict__ x,
                                               const float* __restrict__ W1,
                                               const float* __restrict__ Wl1,
                                               const float* __restrict__ Wr1,
                                               const int* __restrict__ esrc) {
    extern __shared__ uint32_t sm1[];
    uint32_t* sB = sm1;                      // [128][S1P] pair-interleaved
    __shared__ float swl[F1 * H1], swr[F1 * H1];
    int tx = threadIdx.x, lane = tx & 31, w = tx >> 5;

    for (int e = blockIdx.x * 256 + tx; e < Ee; e += gridDim.x * 256)
        atomicAdd(&g_rowptr[esrc[e]], 1);

    for (int i = tx; i < FIN * F1; i += 256) {
        int k = i >> 5, n = i & 31;
        sB[(k >> 1) * S1P + 2 * n + (k & 1)] = f2tf32(W1[i]);
    }
    swl[tx] = Wl1[tx];
    swr[tx] = Wr1[tx];
    __syncthreads();

    {
        int k = tx;
        float sl[H1], sr[H1];
        #pragma unroll
        for (int h = 0; h < H1; h++) { sl[h] = 0.f; sr[h] = 0.f; }
        #pragma unroll 8
        for (int j = 0; j < F1; j++) {
            float v = __uint_as_float(sB[(k >> 1) * S1P + 2 * j + (k & 1)]);
            #pragma unroll
            for (int h = 0; h < H1; h++) {
                sl[h] = fmaf(v, swl[j * H1 + h], sl[h]);
                sr[h] = fmaf(v, swr[j * H1 + h], sr[h]);
            }
        }
        #pragma unroll
        for (int h = 0; h < H1; h++) {
            sB[(k >> 1) * S1P + 2 * (32 + h) + (k & 1)] = f2tf32(sl[h]);
            sB[(k >> 1) * S1P + 2 * (40 + h) + (k & 1)] = f2tf32(sr[h]);
        }
    }
    __syncthreads();

    int g = lane >> 2, c = lane & 3;
    int row0 = blockIdx.x * 128 + w * 16 + g;
    int row1 = row0 + 8;
    bool v0 = row0 < Nn, v1 = row1 < Nn;
    const float4* A0 = (const float4*)(x + (size_t)row0 * FIN);
    const float4* A1 = (const float4*)(x + (size_t)row1 * FIN);
    const float4 z4 = make_float4(0.f, 0.f, 0.f, 0.f);

    float acc[6][4];
    #pragma unroll
    for (int nt = 0; nt < 6; nt++)
        #pragma unroll
        for (int j = 0; j < 4; j++) acc[nt][j] = 0.f;

    float4 b0[4], b1[4];
    #pragma unroll
    for (int t = 0; t < 4; t++) {
        b0[t] = v0 ? A0[t * 4 + c] : z4;
        b1[t] = v1 ? A1[t * 4 + c] : z4;
    }
    #pragma unroll
    for (int ch = 0; ch < 4; ch++) {
        float4 n0[4], n1[4];
        #pragma unroll
        for (int t = 0; t < 4; t++) {
            n0[t] = (v0 && ch < 3) ? A0[(ch + 1) * 16 + t * 4 + c] : z4;
            n1[t] = (v1 && ch < 3) ? A1[(ch + 1) * 16 + t * 4 + c] : z4;
        }
        #pragma unroll
        for (int t = 0; t < 4; t++) {
            int wnd = ch * 4 + t;
            uint32_t a00 = f2tf32(b0[t].x), a01 = f2tf32(b0[t].y), a02 = f2tf32(b0[t].z), a03 = f2tf32(b0[t].w);
            uint32_t a10 = f2tf32(b1[t].x), a11 = f2tf32(b1[t].y), a12 = f2tf32(b1[t].z), a13 = f2tf32(b1[t].w);
            const uint32_t* bP = sB + (wnd * 8 + 2 * c) * S1P + 2 * g;
            #pragma unroll
            for (int nt = 0; nt < 6; nt++) {
                uint2 bb = *(const uint2*)(bP + 16 * nt);
                mma_tf32(acc[nt], a00, a10, a01, a11, bb.x, bb.y);
            }
            const uint32_t* bQ = bP + S1P;
            #pragma unroll
            for (int nt = 0; nt < 6; nt++) {
                uint2 bb = *(const uint2*)(bQ + 16 * nt);
                mma_tf32(acc[nt], a02, a12, a03, a13, bb.x, bb.y);
            }
        }
        #pragma unroll
        for (int t = 0; t < 4; t++) { b0[t] = n0[t]; b1[t] = n1[t]; }
    }
    #pragma unroll
    for (int nt = 0; nt < 4; nt++) {
        if (v0) ((__half2*)g_h1h)[(size_t)row0 * 16 + nt * 4 + c] = __floats2half2_rn(acc[nt][0], acc[nt][1]);
        if (v1) ((__half2*)g_h1h)[(size_t)row1 * 16 + nt * 4 + c] = __floats2half2_rn(acc[nt][2], acc[nt][3]);
    }
    if (v0) *(float2*)&g_el1[row0 * H1 + 2 * c] = make_float2(acc[4][0], acc[4][1]);
    if (v1) *(float2*)&g_el1[row1 * H1 + 2 * c] = make_float2(acc[4][2], acc[4][3]);
    if (v0) ((__half2*)g_er1h)[(size_t)row0 * 4 + c] = __floats2half2_rn(acc[5][0], acc[5][1]);
    if (v1) ((__half2*)g_er1h)[(size_t)row1 * 4 + c] = __floats2half2_rn(acc[5][2], acc[5][3]);
}

// ---------------- fused scan (decoupled lookback) + scatter ----------------
__global__ void k_scan_scatter(const int* __restrict__ src, const int* __restrict__ dst) {
    __shared__ int wsum[32];
    __shared__ int soff;
    int n = Nn + 1;
    int tid = threadIdx.x, b = blockIdx.x;
    int gid = b * 1024 + tid;
    int v = (gid < n) ? g_rowptr[gid] : 0;
    int lane = tid & 31, wid = tid >> 5;
    int x = v;
    #pragma unroll
    for (int d = 1; d < 32; d <<= 1) {
        int t = __shfl_up_sync(0xffffffffu, x, d);
        if (lane >= d) x += t;
    }
    if (lane == 31) wsum[wid] = x;
    __syncthreads();
    if (wid == 0) {
        int w = wsum[lane];
        #pragma unroll
        for (int d = 1; d < 32; d <<= 1) {
            int t = __shfl_up_sync(0xffffffffu, w, d);
            if (lane >= d) w += t;
        }
        wsum[lane] = w;
    }
    __syncthreads();
    int incl = x + (wid > 0 ? wsum[wid - 1] : 0);

    if (tid == 1023) atomicExch(&g_bsums[b], incl);

    if (tid < 32) {
        int p1 = 0, p2 = 0;
        if (tid < b)      { volatile int* p = &g_bsums[tid];      int u; do { u = *p; } while (u == -1); p1 = u; }
        if (tid + 32 < b) { volatile int* p = &g_bsums[tid + 32]; int u; do { u = *p; } while (u == -1); p2 = u; }
        int s = p1 + p2;
        #pragma unroll
        for (int d = 16; d > 0; d >>= 1) s += __shfl_xor_sync(0xffffffffu, s, d);
        if (tid == 0) soff = s;
    }
    __syncthreads();
    if (gid < n) {
        int val = soff + incl - v;
        g_rowptr[gid] = val;
        if (gid < Nn) g_cursor[gid] = val;
    }
    __threadfence();
    __syncthreads();
    if (tid == 0) atomicExch(&g_sflag[b], 1);

    if (tid < 49) { volatile int* p = &g_sflag[tid]; while (*p == 0) {} }
    __syncthreads();

    for (int e = b * 1024 + tid; e < Ee; e += 49 * 1024) {
        int s = src[e];
        int pos = atomicAdd(&g_cursor[s], 1);
        g_csr_dst[pos] = dst[e];
    }
}

// ---------------- layer-1 aggregation via fp16 tensor-core MMA (R13 winner) ----------------
__global__ void __launch_bounds__(256) k_agg1(const float* __restrict__ b1) {
    __shared__ __half sH[8][32 * 40];   // [warp][edge*40 + feat], 80B rows
    __shared__ __half sW[8][32 * 8];    // [warp][edge*8 + head]
    __shared__ float  sD[8][32 * 9];    // den transpose buffer (stride 9)
    int wid = threadIdx.x >> 5, lane = threadIdx.x & 31;
    int i = blockIdx.x * 8 + wid;
    int gr = lane >> 2, tc = lane & 3;

    float el_own = (lane < H1) ? g_el1[i * H1 + lane] : 0.f;
    float elh[H1];
    #pragma unroll
    for (int h = 0; h < H1; h++) elh[h] = __shfl_sync(0xffffffffu, el_own, h);

    float denp[H1];
    #pragma unroll
    for (int h = 0; h < H1; h++) denp[h] = 0.f;
    float acc[4][4];
    #pragma unroll
    for (int nc = 0; nc < 4; nc++)
        #pragma unroll
        for (int j = 0; j < 4; j++) acc[nc][j] = 0.f;

    uint32_t aW = (uint32_t)__cvta_generic_to_shared(&sW[wid][lane * 8]);
    int eloc  = ((lane >> 3) & 1) * 8 + (lane & 7);
    int fbase = (lane >> 4) * 8;
    uint32_t aH = (uint32_t)__cvta_generic_to_shared(&sH[wid][eloc * 40 + fbase]);

    int beg = g_rowptr[i], end = g_rowptr[i + 1];
    for (int base = beg; base < end; base += 32) {
        int nb = min(32, end - base);
        int dstl = (lane < nb) ? g_csr_dst[base + lane] : 0;

        float w_own[H1];
        if (lane < nb) {
            uint4 rv = *(const uint4*)(g_er1h + dstl * H1);
            __half2 e0 = *(__half2*)&rv.x, e1 = *(__half2*)&rv.y;
            __half2 e2 = *(__half2*)&rv.z, e3 = *(__half2*)&rv.w;
            float er_[H1] = {__low2float(e0), __high2float(e0), __low2float(e1), __high2float(e1),
                             __low2float(e2), __high2float(e2), __low2float(e3), __high2float(e3)};
            #pragma unroll
            for (int h = 0; h < H1; h++) {
                float a = elh[h] + er_[h];
                float lr = a > 0.f ? a : 0.2f * a;
                float wv = __expf(lr);
                w_own[h] = wv;
                denp[h] += wv;
            }
        } else {
            #pragma unroll
            for (int h = 0; h < H1; h++) w_own[h] = 0.f;
        }
        {
            uint4 wp;
            __half2 p0 = __floats2half2_rn(w_own[0], w_own[1]);
            __half2 p1 = __floats2half2_rn(w_own[2], w_own[3]);
            __half2 p2 = __floats2half2_rn(w_own[4], w_own[5]);
            __half2 p3 = __floats2half2_rn(w_own[6], w_own[7]);
            wp.x = *(uint32_t*)&p0; wp.y = *(uint32_t*)&p1;
            wp.z = *(uint32_t*)&p2; wp.w = *(uint32_t*)&p3;
            *(uint4*)&sW[wid][lane * 8] = wp;
        }
        {
            const uint4* hr = (const uint4*)(g_h1h + dstl * F1);
            uint4 q0 = hr[0], q1 = hr[1], q2 = hr[2], q3 = hr[3];
            uint4* srow = (uint4*)&sH[wid][lane * 40];
            srow[0] = q0; srow[1] = q1; srow[2] = q2; srow[3] = q3;
        }
        __syncwarp();

        uint32_t A0, A1, A2, A3;
        ldmatrix_x4_trans(A0, A1, A2, A3, aW);

        uint32_t B0, B1, B2, B3;
        ldmatrix_x4_trans(B0, B1, B2, B3, aH);
        mma_f16(acc[0], A0, 0u, A1, 0u, B0, B1);
        mma_f16(acc[1], A0, 0u, A1, 0u, B2, B3);
        ldmatrix_x4_trans(B0, B1, B2, B3, aH + 32);
        mma_f16(acc[2], A0, 0u, A1, 0u, B0, B1);
        mma_f16(acc[3], A0, 0u, A1, 0u, B2, B3);

        if (nb > 16) {
            ldmatrix_x4_trans(B0, B1, B2, B3, aH + 1280);
            mma_f16(acc[0], A2, 0u, A3, 0u, B0, B1);
            mma_f16(acc[1], A2, 0u, A3, 0u, B2, B3);
            ldmatrix_x4_trans(B0, B1, B2, B3, aH + 1280 + 32);
            mma_f16(acc[2], A2, 0u, A3, 0u, B0, B1);
            mma_f16(acc[3], A2, 0u, A3, 0u, B2, B3);
        }
        __syncwarp();
    }

    #pragma unroll
    for (int h = 0; h < H1; h++) sD[wid][lane * 9 + h] = denp[h];
    __syncwarp();
    float part = 0.f;
    #pragma unroll
    for (int m = 0; m < 8; m++) part += sD[wid][(tc * 8 + m) * 9 + gr];
    part += __shfl_xor_sync(0xffffffffu, part, 1);
    part += __shfl_xor_sync(0xffffffffu, part, 2);
    float rden = __fdividef(1.f, fmaxf(part, 1e-12f));

    __half2* r1h2 = (__half2*)g_r1h;
    #pragma unroll
    for (int nc = 0; nc < 4; nc++) {
        float2 bb = ((const float2*)b1)[nc * 4 + tc];
        float o0 = fmaf(acc[nc][0], rden, bb.x);
        float o1 = fmaf(acc[nc][1], rden, bb.y);
        float e0 = o0 > 0.f ? o0 : (__expf(o0) - 1.f);
        float e1 = o1 > 0.f ? o1 : (__expf(o1) - 1.f);
        r1h2[i * 128 + gr * 16 + nc * 4 + tc] = __floats2half2_rn(e0, e1);
    }
}

// ---------------- GEMM2 (tf32, fused B prep, fp16 A from r1h) ----------------
#define S2P 116
__global__ void __launch_bounds__(256) k_gemm2(const float* __restrict__ W2,
                                               const float* __restrict__ Wl2,
                                               const float* __restrict__ Wr2) {
    extern __shared__ uint32_t sm2[];
    uint32_t* sB = sm2;                      // [128][S2P]
    __shared__ float swl2[NC], swr2[NC];
    int tx = threadIdx.x, lane = tx & 31, w = tx >> 5;
    if (tx < NC) { swl2[tx] = Wl2[tx]; swr2[tx] = Wr2[tx]; }
    __syncthreads();
    {
        int k = tx;
        float sl = 0.f, sr = 0.f;
        #pragma unroll 4
        for (int j = 0; j < NC; j++) {
            float v = W2[k * NC + j];
            sB[(k >> 1) * S2P + 2 * j + (k & 1)] = f2tf32(v);
            sl = fmaf(v, swl2[j], sl);
            sr = fmaf(v, swr2[j], sr);
        }
        sB[(k >> 1) * S2P + 2 * 47 + (k & 1)] = 0u;
        sB[(k >> 1) * S2P + 2 * 48 + (k & 1)] = f2tf32(sl);
        sB[(k >> 1) * S2P + 2 * 49 + (k & 1)] = f2tf32(sr);
        #pragma unroll
        for (int j = 50; j < 56; j++) sB[(k >> 1) * S2P + 2 * j + (k & 1)] = 0u;
    }
    __syncthreads();

    int g = lane >> 2, c = lane & 3;
    int row0 = blockIdx.x * 128 + w * 16 + g;
    int row1 = row0 + 8;
    bool v0 = row0 < Nn, v1 = row1 < Nn;
    const uint2* A0 = (const uint2*)(g_r1h + (size_t)row0 * FIN);
    const uint2* A1 = (const uint2*)(g_r1h + (size_t)row1 * FIN);
    const uint2 z2 = make_uint2(0u, 0u);

    float acc[7][4];
    #pragma unroll
    for (int nt = 0; nt < 7; nt++)
        #pragma unroll
        for (int j = 0; j < 4; j++) acc[nt][j] = 0.f;

    uint2 b0[4], b1[4];
    #pragma unroll
    for (int t = 0; t < 4; t++) {
        b0[t] = v0 ? A0[t * 4 + c] : z2;
        b1[t] = v1 ? A1[t * 4 + c] : z2;
    }
    #pragma unroll
    for (int ch = 0; ch < 4; ch++) {
        uint2 n0[4], n1[4];
        #pragma unroll
        for (int t = 0; t < 4; t++) {
            n0[t] = (v0 && ch < 3) ? A0[(ch + 1) * 16 + t * 4 + c] : z2;
            n1[t] = (v1 && ch < 3) ? A1[(ch + 1) * 16 + t * 4 + c] : z2;
        }
        #pragma unroll
        for (int t = 0; t < 4; t++) {
            int wnd = ch * 4 + t;
            float4 fa0 = h4_to_f4(b0[t]);
            float4 fa1 = h4_to_f4(b1[t]);
            uint32_t a00 = f2tf32(fa0.x), a01 = f2tf32(fa0.y), a02 = f2tf32(fa0.z), a03 = f2tf32(fa0.w);
            uint32_t a10 = f2tf32(fa1.x), a11 = f2tf32(fa1.y), a12 = f2tf32(fa1.z), a13 = f2tf32(fa1.w);
            const uint32_t* bP = sB + (wnd * 8 + 2 * c) * S2P + 2 * g;
            #pragma unroll
            for (int nt = 0; nt < 7; nt++) {
                uint2 bb = *(const uint2*)(bP + 16 * nt);
                mma_tf32(acc[nt], a00, a10, a01, a11, bb.x, bb.y);
            }
            const uint32_t* bQ = bP + S2P;
            #pragma unroll
            for (int nt = 0; nt < 7; nt++) {
                uint2 bb = *(const uint2*)(bQ + 16 * nt);
                mma_tf32(acc[nt], a02, a12, a03, a13, bb.x, bb.y);
            }
        }
        #pragma unroll
        for (int t = 0; t < 4; t++) { b0[t] = n0[t]; b1[t] = n1[t]; }
    }
    #pragma unroll
    for (int nt = 0; nt < 7; nt++) {
        int col = nt * 8 + 2 * c;
        if (col < 48) {
            if (v0) ((__half2*)g_h2ph)[(size_t)row0 * 24 + nt * 4 + c] = __floats2half2_rn(acc[nt][0], acc[nt][1]);
            if (v1) ((__half2*)g_h2ph)[(size_t)row1 * 24 + nt * 4 + c] = __floats2half2_rn(acc[nt][2], acc[nt][3]);
        } else if (col == 48) {
            if (v0) { g_el2[row0] = acc[nt][0]; g_er2[row0] = acc[nt][1]; }
            if (v1) { g_el2[row1] = acc[nt][2]; g_er2[row1] = acc[nt][3]; }
        }
    }
}

// ---------------- layer-2 aggregation via fp16 tensor-core MMA + log_softmax ----------------
// A = weights in row 0 of 16x32 tile, built in registers (no smem, no A-ldmatrix).
// B = gathered h2p rows (48 feats, stride 56 halves = 112B; ldmatrix row banks distinct).
// Result lives in lanes 0-3 (gr==0): lane tc holds feats nc*8+2tc, +1 (nc=0..5).
__global__ void __launch_bounds__(256) k_agg2(const float* __restrict__ b2, float* __restrict__ out) {
    __shared__ __half sH[8][32 * 56];   // [warp][edge*56 + feat]
    int wid = threadIdx.x >> 5, lane = threadIdx.x & 31;
    int i = blockIdx.x * 8 + wid;
    int gr = lane >> 2, tc = lane & 3;

    // zero-init sH (guarded gathers may leave stale/uninit rows; 0 x NaN = NaN)
    {
        uint4* z = (uint4*)&sH[wid][0];
        const uint4 zz = make_uint4(0u, 0u, 0u, 0u);
        #pragma unroll
        for (int j = 0; j < 7; j++) z[j * 32 + lane] = zz;
    }

    float el = g_el2[i];
    float denp = 0.f;
    float acc[6][4];
    #pragma unroll
    for (int nc = 0; nc < 6; nc++)
        #pragma unroll
        for (int j = 0; j < 4; j++) acc[nc][j] = 0.f;

    int eloc  = ((lane >> 3) & 1) * 8 + (lane & 7);
    int fbase = (lane >> 4) * 8;
    uint32_t aH = (uint32_t)__cvta_generic_to_shared(&sH[wid][eloc * 56 + fbase]);
    uint4* srow = (uint4*)&sH[wid][lane * 56];

    int beg = g_rowptr[i], end = g_rowptr[i + 1];
    for (int base = beg; base < end; base += 32) {
        int nb = min(32, end - base);
        int dstl = (lane < nb) ? g_csr_dst[base + lane] : 0;
        float wl_ = 0.f;
        if (lane < nb) {
            float a = el + g_er2[dstl];
            float lr = a > 0.f ? a : 0.2f * a;
            wl_ = __expf(lr);
            denp += wl_;
            const uint4* hr = (const uint4*)(g_h2ph + (size_t)dstl * 48);
            #pragma unroll
            for (int q = 0; q < 6; q++) srow[q] = hr[q];
        }
        __syncwarp();

        #pragma unroll
        for (int kc = 0; kc < 2; kc++) {
            if (kc == 1 && nb <= 16) break;
            int e0 = kc * 16;
            // A row-0 fragment built via shfl: a0 = w[e0+2tc, e0+2tc+1], a2 = w[e0+8+2tc, +1]
            float wl0 = __shfl_sync(0xffffffffu, wl_, e0 + 2 * tc);
            float wh0 = __shfl_sync(0xffffffffu, wl_, e0 + 2 * tc + 1);
            float wl1 = __shfl_sync(0xffffffffu, wl_, e0 + 8 + 2 * tc);
            float wh1 = __shfl_sync(0xffffffffu, wl_, e0 + 9 + 2 * tc);
            __half2 p0 = __floats2half2_rn(wl0, wh0);
            __half2 p2 = __floats2half2_rn(wl1, wh1);
            uint32_t a0 = (gr == 0) ? *(uint32_t*)&p0 : 0u;
            uint32_t a2 = (gr == 0) ? *(uint32_t*)&p2 : 0u;
            uint32_t bA = aH + kc * 1792;   // +16 rows * 112B
            uint32_t B0, B1, B2, B3;
            ldmatrix_x4_trans(B0, B1, B2, B3, bA);
            mma_f16(acc[0], a0, 0u, a2, 0u, B0, B1);
            mma_f16(acc[1], a0, 0u, a2, 0u, B2, B3);
            ldmatrix_x4_trans(B0, B1, B2, B3, bA + 32);
            mma_f16(acc[2], a0, 0u, a2, 0u, B0, B1);
            mma_f16(acc[3], a0, 0u, a2, 0u, B2, B3);
            ldmatrix_x4_trans(B0, B1, B2, B3, bA + 64);
            mma_f16(acc[4], a0, 0u, a2, 0u, B0, B1);
            mma_f16(acc[5], a0, 0u, a2, 0u, B2, B3);
        }
        __syncwarp();
    }

    // denominator: full-warp butterfly
    float den = denp;
    #pragma unroll
    for (int d = 16; d > 0; d >>= 1) den += __shfl_xor_sync(0xffffffffu, den, d);
    float rden = __fdividef(1.f, fmaxf(den, 1e-12f));

    // log_softmax among lanes 0-3 (each holds 12 feats: nc*8+2tc, +1)
    float v[6][2];
    float m = -3.0e38f;
    #pragma unroll
    for (int nc = 0; nc < 6; nc++) {
        #pragma unroll
        for (int j = 0; j < 2; j++) {
            int f = nc * 8 + 2 * tc + j;
            if (f < NC) {
                v[nc][j] = fmaf(acc[nc][j], rden, b2[f]);
                m = fmaxf(m, v[nc][j]);
            } else {
                v[nc][j] = -3.0e38f;
            }
        }
    }
    m = fmaxf(m, __shfl_xor_sync(0xffffffffu, m, 1));
    m = fmaxf(m, __shfl_xor_sync(0xffffffffu, m, 2));
    float s = 0.f;
    #pragma unroll
    for (int nc = 0; nc < 6; nc++) {
        #pragma unroll
        for (int j = 0; j < 2; j++) {
            int f = nc * 8 + 2 * tc + j;
            if (f < NC) s += __expf(v[nc][j] - m);
        }
    }
    s += __shfl_xor_sync(0xffffffffu, s, 1);
    s += __shfl_xor_sync(0xffffffffu, s, 2);
    float ls = logf(s);
    if (gr == 0) {
        #pragma unroll
        for (int nc = 0; nc < 6; nc++) {
            #pragma unroll
            for (int j = 0; j < 2; j++) {
                int f = nc * 8 + 2 * tc + j;
                if (f < NC) out[(size_t)i * NC + f] = v[nc][j] - m - ls;
            }
        }
    }
}

// ---------------- launch (6 kernels; #4 = k_agg1 -> profiled) ----------------
extern "C" void kernel_launch(void* const* d_in, const int* in_sizes, int n_in,
                              void* d_out, int out_size) {
    const float* x    = (const float*)d_in[0];
    const int*   esrc = (const int*)  d_in[1];
    const int*   edst = (const int*)  d_in[2];
    const float* W1   = (const float*)d_in[3];
    const float* Wl1  = (const float*)d_in[4];
    const float* Wr1  = (const float*)d_in[5];
    const float* b1   = (const float*)d_in[6];
    const float* W2   = (const float*)d_in[7];
    const float* Wl2  = (const float*)d_in[8];
    const float* Wr2  = (const float*)d_in[9];
    const float* b2   = (const float*)d_in[10];
    float* out = (float*)d_out;

    const int smem1 = 128 * S1P * 4;   // 51.2 KB
    const int smem2 = 128 * S2P * 4;   // 59.4 KB
    cudaFuncSetAttribute(k_gemm1, cudaFuncAttributeMaxDynamicSharedMemorySize, smem1);
    cudaFuncSetAttribute(k_gemm2, cudaFuncAttributeMaxDynamicSharedMemorySize, smem2);

    k_zero<<<(Nn + 1 + 255) / 256, 256>>>();
    k_gemm1<<<(Nn + 127) / 128, 256, smem1>>>(x, W1, Wl1, Wr1, esrc);
    k_scan_scatter<<<49, 1024>>>(esrc, edst);
    k_agg1<<<Nn / 8, 256>>>(b1);                    // #4 <- profiled
    k_gemm2<<<(Nn + 127) / 128, 256, smem2>>>(W2, Wl2, Wr2);
    k_agg2<<<Nn / 8, 256>>>(b2, out);
}

// round 16
// speedup vs baseline: 1.1060x; 1.1060x over previous
#include <cuda_runtime.h>
#include <cuda_fp16.h>
#include <cstdint>

#define Nn 50000
#define Ee 800000
#define FIN 256
#define F1 32
#define H1 8
#define NHID 256
#define NC 47

// ---------------- scratch (device globals: allocation-free) ----------------
__device__ int    g_rowptr[Nn + 1];
__device__ int    g_cursor[Nn];
__device__ int    g_csr_dst[Ee];
__device__ int    g_bsums[64];
__device__ int    g_sflag[64];
__device__ __half g_h1h[Nn * F1];        // 3.2 MB fp16 gather array (layer 1)
__device__ float  g_el1[Nn * H1];
__device__ __half g_er1h[Nn * H1];       // 0.8 MB fp16 gather array
__device__ __half g_r1h[Nn * NHID];      // 25.6 MB fp16 hidden activations
__device__ __half g_h2ph[Nn * 48];       // 4.8 MB fp16 gather array (layer 2)
__device__ float  g_el2[Nn];
__device__ float  g_er2[Nn];

// ---------------- tf32 mma helpers ----------------
__device__ __forceinline__ uint32_t f2tf32(float f) {
    uint32_t r;
    asm("cvt.rna.tf32.f32 %0, %1;" : "=r"(r) : "f"(f));
    return r;
}

__device__ __forceinline__ void mma_tf32(float* d,
    uint32_t a0, uint32_t a1, uint32_t a2, uint32_t a3,
    uint32_t b0, uint32_t b1) {
    asm volatile(
        "mma.sync.aligned.m16n8k8.row.col.f32.tf32.tf32.f32 "
        "{%0,%1,%2,%3},{%4,%5,%6,%7},{%8,%9},{%0,%1,%2,%3};\n"
        : "+f"(d[0]), "+f"(d[1]), "+f"(d[2]), "+f"(d[3])
        : "r"(a0), "r"(a1), "r"(a2), "r"(a3), "r"(b0), "r"(b1));
}

// fp16 mma m16n8k16, fp32 accumulate
__device__ __forceinline__ void mma_f16(float* d,
    uint32_t a0, uint32_t a1, uint32_t a2, uint32_t a3,
    uint32_t b0, uint32_t b1) {
    asm volatile(
        "mma.sync.aligned.m16n8k16.row.col.f32.f16.f16.f32 "
        "{%0,%1,%2,%3},{%4,%5,%6,%7},{%8,%9},{%0,%1,%2,%3};\n"
        : "+f"(d[0]), "+f"(d[1]), "+f"(d[2]), "+f"(d[3])
        : "r"(a0), "r"(a1), "r"(a2), "r"(a3), "r"(b0), "r"(b1));
}

__device__ __forceinline__ void ldmatrix_x4_trans(uint32_t& r0, uint32_t& r1,
                                                  uint32_t& r2, uint32_t& r3,
                                                  uint32_t addr) {
    asm volatile("ldmatrix.sync.aligned.m8n8.x4.trans.shared.b16 {%0,%1,%2,%3}, [%4];"
        : "=r"(r0), "=r"(r1), "=r"(r2), "=r"(r3) : "r"(addr));
}

__device__ __forceinline__ float4 h4_to_f4(uint2 r) {
    __half2 p0 = *(__half2*)&r.x, p1 = *(__half2*)&r.y;
    return make_float4(__low2float(p0), __high2float(p0),
                       __low2float(p1), __high2float(p1));
}

// ---------------- zero / sentinel init ----------------
__global__ void k_zero() {
    int i = blockIdx.x * 256 + threadIdx.x;
    if (i < Nn + 1) g_rowptr[i] = 0;
    if (i < 64) { g_bsums[i] = -1; g_sflag[i] = 0; }
}

// ---------------- GEMM1 (tf32, fused: edge count + B prep + MMA) ----------------
#define S1P 100
__global__ void __launch_bounds__(256) k_gemm1(const float* __restrict__ x,
                                               const float* __restrict__ W1,
                                               const float* __restrict__ Wl1,
                                               const float* __restrict__ Wr1,
                                               const int* __restrict__ esrc) {
    extern __shared__ uint32_t sm1[];
    uint32_t* sB = sm1;                      // [128][S1P] pair-interleaved
    __shared__ float swl[F1 * H1], swr[F1 * H1];
    int tx = threadIdx.x, lane = tx & 31, w = tx >> 5;

    for (int e = blockIdx.x * 256 + tx; e < Ee; e += gridDim.x * 256)
        atomicAdd(&g_rowptr[esrc[e]], 1);

    for (int i = tx; i < FIN * F1; i += 256) {
        int k = i >> 5, n = i & 31;
        sB[(k >> 1) * S1P + 2 * n + (k & 1)] = f2tf32(W1[i]);
    }
    swl[tx] = Wl1[tx];
    swr[tx] = Wr1[tx];
    __syncthreads();

    {
        int k = tx;
        float sl[H1], sr[H1];
        #pragma unroll
        for (int h = 0; h < H1; h++) { sl[h] = 0.f; sr[h] = 0.f; }
        #pragma unroll 8
        for (int j = 0; j < F1; j++) {
            float v = __uint_as_float(sB[(k >> 1) * S1P + 2 * j + (k & 1)]);
            #pragma unroll
            for (int h = 0; h < H1; h++) {
                sl[h] = fmaf(v, swl[j * H1 + h], sl[h]);
                sr[h] = fmaf(v, swr[j * H1 + h], sr[h]);
            }
        }
        #pragma unroll
        for (int h = 0; h < H1; h++) {
            sB[(k >> 1) * S1P + 2 * (32 + h) + (k & 1)] = f2tf32(sl[h]);
            sB[(k >> 1) * S1P + 2 * (40 + h) + (k & 1)] = f2tf32(sr[h]);
        }
    }
    __syncthreads();

    int g = lane >> 2, c = lane & 3;
    int row0 = blockIdx.x * 128 + w * 16 + g;
    int row1 = row0 + 8;
    bool v0 = row0 < Nn, v1 = row1 < Nn;
    const float4* A0 = (const float4*)(x + (size_t)row0 * FIN);
    const float4* A1 = (const float4*)(x + (size_t)row1 * FIN);
    const float4 z4 = make_float4(0.f, 0.f, 0.f, 0.f);

    float acc[6][4];
    #pragma unroll
    for (int nt = 0; nt < 6; nt++)
        #pragma unroll
        for (int j = 0; j < 4; j++) acc[nt][j] = 0.f;

    float4 b0[4], b1[4];
    #pragma unroll
    for (int t = 0; t < 4; t++) {
        b0[t] = v0 ? A0[t * 4 + c] : z4;
        b1[t] = v1 ? A1[t * 4 + c] : z4;
    }
    #pragma unroll
    for (int ch = 0; ch < 4; ch++) {
        float4 n0[4], n1[4];
        #pragma unroll
        for (int t = 0; t < 4; t++) {
            n0[t] = (v0 && ch < 3) ? A0[(ch + 1) * 16 + t * 4 + c] : z4;
            n1[t] = (v1 && ch < 3) ? A1[(ch + 1) * 16 + t * 4 + c] : z4;
        }
        #pragma unroll
        for (int t = 0; t < 4; t++) {
            int wnd = ch * 4 + t;
            uint32_t a00 = f2tf32(b0[t].x), a01 = f2tf32(b0[t].y), a02 = f2tf32(b0[t].z), a03 = f2tf32(b0[t].w);
            uint32_t a10 = f2tf32(b1[t].x), a11 = f2tf32(b1[t].y), a12 = f2tf32(b1[t].z), a13 = f2tf32(b1[t].w);
            const uint32_t* bP = sB + (wnd * 8 + 2 * c) * S1P + 2 * g;
            #pragma unroll
            for (int nt = 0; nt < 6; nt++) {
                uint2 bb = *(const uint2*)(bP + 16 * nt);
                mma_tf32(acc[nt], a00, a10, a01, a11, bb.x, bb.y);
            }
            const uint32_t* bQ = bP + S1P;
            #pragma unroll
            for (int nt = 0; nt < 6; nt++) {
                uint2 bb = *(const uint2*)(bQ + 16 * nt);
                mma_tf32(acc[nt], a02, a12, a03, a13, bb.x, bb.y);
            }
        }
        #pragma unroll
        for (int t = 0; t < 4; t++) { b0[t] = n0[t]; b1[t] = n1[t]; }
    }
    #pragma unroll
    for (int nt = 0; nt < 4; nt++) {
        if (v0) ((__half2*)g_h1h)[(size_t)row0 * 16 + nt * 4 + c] = __floats2half2_rn(acc[nt][0], acc[nt][1]);
        if (v1) ((__half2*)g_h1h)[(size_t)row1 * 16 + nt * 4 + c] = __floats2half2_rn(acc[nt][2], acc[nt][3]);
    }
    if (v0) *(float2*)&g_el1[row0 * H1 + 2 * c] = make_float2(acc[4][0], acc[4][1]);
    if (v1) *(float2*)&g_el1[row1 * H1 + 2 * c] = make_float2(acc[4][2], acc[4][3]);
    if (v0) ((__half2*)g_er1h)[(size_t)row0 * 4 + c] = __floats2half2_rn(acc[5][0], acc[5][1]);
    if (v1) ((__half2*)g_er1h)[(size_t)row1 * 4 + c] = __floats2half2_rn(acc[5][2], acc[5][3]);
}

// ---------------- fused scan (decoupled lookback) + scatter ----------------
__global__ void k_scan_scatter(const int* __restrict__ src, const int* __restrict__ dst) {
    __shared__ int wsum[32];
    __shared__ int soff;
    int n = Nn + 1;
    int tid = threadIdx.x, b = blockIdx.x;
    int gid = b * 1024 + tid;
    int v = (gid < n) ? g_rowptr[gid] : 0;
    int lane = tid & 31, wid = tid >> 5;
    int x = v;
    #pragma unroll
    for (int d = 1; d < 32; d <<= 1) {
        int t = __shfl_up_sync(0xffffffffu, x, d);
        if (lane >= d) x += t;
    }
    if (lane == 31) wsum[wid] = x;
    __syncthreads();
    if (wid == 0) {
        int w = wsum[lane];
        #pragma unroll
        for (int d = 1; d < 32; d <<= 1) {
            int t = __shfl_up_sync(0xffffffffu, w, d);
            if (lane >= d) w += t;
        }
        wsum[lane] = w;
    }
    __syncthreads();
    int incl = x + (wid > 0 ? wsum[wid - 1] : 0);

    if (tid == 1023) atomicExch(&g_bsums[b], incl);

    if (tid < 32) {
        int p1 = 0, p2 = 0;
        if (tid < b)      { volatile int* p = &g_bsums[tid];      int u; do { u = *p; } while (u == -1); p1 = u; }
        if (tid + 32 < b) { volatile int* p = &g_bsums[tid + 32]; int u; do { u = *p; } while (u == -1); p2 = u; }
        int s = p1 + p2;
        #pragma unroll
        for (int d = 16; d > 0; d >>= 1) s += __shfl_xor_sync(0xffffffffu, s, d);
        if (tid == 0) soff = s;
    }
    __syncthreads();
    if (gid < n) {
        int val = soff + incl - v;
        g_rowptr[gid] = val;
        if (gid < Nn) g_cursor[gid] = val;
    }
    __threadfence();
    __syncthreads();
    if (tid == 0) atomicExch(&g_sflag[b], 1);

    if (tid < 49) { volatile int* p = &g_sflag[tid]; while (*p == 0) {} }
    __syncthreads();

    for (int e = b * 1024 + tid; e < Ee; e += 49 * 1024) {
        int s = src[e];
        int pos = atomicAdd(&g_cursor[s], 1);
        g_csr_dst[pos] = dst[e];
    }
}

// ---------------- layer-1 aggregation: fp16 MMA + cooperative 4-lane gather ----------------
// Gather: lane (t=l>>2, c=l&3) loads 16B chunk c of edge ep = p*8 + perm(t),
// perm(t)=(t&1)*4+(t>>1) pairs edges {e,e+4} per 8-lane phase -> conflict-free STS
// and 1 line per edge row (rows 64B-aligned). Passes limited to ceil(nb/8)/... :
// nb<=16 -> 2 passes; ungathered rows never read (kc=1 MMA skipped).
__global__ void __launch_bounds__(256) k_agg1(const float* __restrict__ b1) {
    __shared__ __half sH[8][32 * 40];   // [warp][edge*40 + feat], 80B rows
    __shared__ __half sW[8][32 * 8];    // [warp][edge*8 + head]
    __shared__ float  sD[8][32 * 9];    // den transpose buffer (stride 9)
    int wid = threadIdx.x >> 5, lane = threadIdx.x & 31;
    int i = blockIdx.x * 8 + wid;
    int gr = lane >> 2, tc = lane & 3;
    int tq = lane >> 2, cq = lane & 3;
    int ep_base = (tq & 1) * 4 + (tq >> 1);   // 0,4,1,5,2,6,3,7

    float el_own = (lane < H1) ? g_el1[i * H1 + lane] : 0.f;
    float elh[H1];
    #pragma unroll
    for (int h = 0; h < H1; h++) elh[h] = __shfl_sync(0xffffffffu, el_own, h);

    float denp[H1];
    #pragma unroll
    for (int h = 0; h < H1; h++) denp[h] = 0.f;
    float acc[4][4];
    #pragma unroll
    for (int nc = 0; nc < 4; nc++)
        #pragma unroll
        for (int j = 0; j < 4; j++) acc[nc][j] = 0.f;

    uint32_t aW = (uint32_t)__cvta_generic_to_shared(&sW[wid][lane * 8]);
    int eloc  = ((lane >> 3) & 1) * 8 + (lane & 7);
    int fbase = (lane >> 4) * 8;
    uint32_t aH = (uint32_t)__cvta_generic_to_shared(&sH[wid][eloc * 40 + fbase]);

    int beg = g_rowptr[i], end = g_rowptr[i + 1];
    for (int base = beg; base < end; base += 32) {
        int nb = min(32, end - base);
        int dstl = (lane < nb) ? g_csr_dst[base + lane] : 0;

        // weights: exp(lrelu(el+er)) per head for this lane's edge
        float w_own[H1];
        if (lane < nb) {
            uint4 rv = *(const uint4*)(g_er1h + dstl * H1);
            __half2 e0 = *(__half2*)&rv.x, e1 = *(__half2*)&rv.y;
            __half2 e2 = *(__half2*)&rv.z, e3 = *(__half2*)&rv.w;
            float er_[H1] = {__low2float(e0), __high2float(e0), __low2float(e1), __high2float(e1),
                             __low2float(e2), __high2float(e2), __low2float(e3), __high2float(e3)};
            #pragma unroll
            for (int h = 0; h < H1; h++) {
                float a = elh[h] + er_[h];
                float lr = a > 0.f ? a : 0.2f * a;
                float wv = __expf(lr);
                w_own[h] = wv;
                denp[h] += wv;
            }
        } else {
            #pragma unroll
            for (int h = 0; h < H1; h++) w_own[h] = 0.f;
        }
        {
            uint4 wp;
            __half2 p0 = __floats2half2_rn(w_own[0], w_own[1]);
            __half2 p1 = __floats2half2_rn(w_own[2], w_own[3]);
            __half2 p2 = __floats2half2_rn(w_own[4], w_own[5]);
            __half2 p3 = __floats2half2_rn(w_own[6], w_own[7]);
            wp.x = *(uint32_t*)&p0; wp.y = *(uint32_t*)&p1;
            wp.z = *(uint32_t*)&p2; wp.w = *(uint32_t*)&p3;
            *(uint4*)&sW[wid][lane * 8] = wp;
        }
        // cooperative gather: 4 lanes per edge row, 8 edges per pass
        int npass = (nb > 16) ? 4 : 2;
        for (int p = 0; p < npass; p++) {
            int ep = p * 8 + ep_base;
            int de = __shfl_sync(0xffffffffu, dstl, ep);
            uint4 q = *(const uint4*)(g_h1h + de * F1 + cq * 8);
            *(uint4*)&sH[wid][ep * 40 + cq * 8] = q;
        }
        __syncwarp();

        uint32_t A0, A1, A2, A3;
        ldmatrix_x4_trans(A0, A1, A2, A3, aW);

        uint32_t B0, B1, B2, B3;
        ldmatrix_x4_trans(B0, B1, B2, B3, aH);
        mma_f16(acc[0], A0, 0u, A1, 0u, B0, B1);
        mma_f16(acc[1], A0, 0u, A1, 0u, B2, B3);
        ldmatrix_x4_trans(B0, B1, B2, B3, aH + 32);
        mma_f16(acc[2], A0, 0u, A1, 0u, B0, B1);
        mma_f16(acc[3], A0, 0u, A1, 0u, B2, B3);

        if (nb > 16) {
            ldmatrix_x4_trans(B0, B1, B2, B3, aH + 1280);
            mma_f16(acc[0], A2, 0u, A3, 0u, B0, B1);
            mma_f16(acc[1], A2, 0u, A3, 0u, B2, B3);
            ldmatrix_x4_trans(B0, B1, B2, B3, aH + 1280 + 32);
            mma_f16(acc[2], A2, 0u, A3, 0u, B0, B1);
            mma_f16(acc[3], A2, 0u, A3, 0u, B2, B3);
        }
        __syncwarp();
    }

    #pragma unroll
    for (int h = 0; h < H1; h++) sD[wid][lane * 9 + h] = denp[h];
    __syncwarp();
    float part = 0.f;
    #pragma unroll
    for (int m = 0; m < 8; m++) part += sD[wid][(tc * 8 + m) * 9 + gr];
    part += __shfl_xor_sync(0xffffffffu, part, 1);
    part += __shfl_xor_sync(0xffffffffu, part, 2);
    float rden = __fdividef(1.f, fmaxf(part, 1e-12f));

    __half2* r1h2 = (__half2*)g_r1h;
    #pragma unroll
    for (int nc = 0; nc < 4; nc++) {
        float2 bb = ((const float2*)b1)[nc * 4 + tc];
        float o0 = fmaf(acc[nc][0], rden, bb.x);
        float o1 = fmaf(acc[nc][1], rden, bb.y);
        float e0 = o0 > 0.f ? o0 : (__expf(o0) - 1.f);
        float e1 = o1 > 0.f ? o1 : (__expf(o1) - 1.f);
        r1h2[i * 128 + gr * 16 + nc * 4 + tc] = __floats2half2_rn(e0, e1);
    }
}

// ---------------- GEMM2 (tf32, fused B prep, fp16 A from r1h) ----------------
#define S2P 116
__global__ void __launch_bounds__(256) k_gemm2(const float* __restrict__ W2,
                                               const float* __restrict__ Wl2,
                                               const float* __restrict__ Wr2) {
    extern __shared__ uint32_t sm2[];
    uint32_t* sB = sm2;                      // [128][S2P]
    __shared__ float swl2[NC], swr2[NC];
    int tx = threadIdx.x, lane = tx & 31, w = tx >> 5;
    if (tx < NC) { swl2[tx] = Wl2[tx]; swr2[tx] = Wr2[tx]; }
    __syncthreads();
    {
        int k = tx;
        float sl = 0.f, sr = 0.f;
        #pragma unroll 4
        for (int j = 0; j < NC; j++) {
            float v = W2[k * NC + j];
            sB[(k >> 1) * S2P + 2 * j + (k & 1)] = f2tf32(v);
            sl = fmaf(v, swl2[j], sl);
            sr = fmaf(v, swr2[j], sr);
        }
        sB[(k >> 1) * S2P + 2 * 47 + (k & 1)] = 0u;
        sB[(k >> 1) * S2P + 2 * 48 + (k & 1)] = f2tf32(sl);
        sB[(k >> 1) * S2P + 2 * 49 + (k & 1)] = f2tf32(sr);
        #pragma unroll
        for (int j = 50; j < 56; j++) sB[(k >> 1) * S2P + 2 * j + (k & 1)] = 0u;
    }
    __syncthreads();

    int g = lane >> 2, c = lane & 3;
    int row0 = blockIdx.x * 128 + w * 16 + g;
    int row1 = row0 + 8;
    bool v0 = row0 < Nn, v1 = row1 < Nn;
    const uint2* A0 = (const uint2*)(g_r1h + (size_t)row0 * FIN);
    const uint2* A1 = (const uint2*)(g_r1h + (size_t)row1 * FIN);
    const uint2 z2 = make_uint2(0u, 0u);

    float acc[7][4];
    #pragma unroll
    for (int nt = 0; nt < 7; nt++)
        #pragma unroll
        for (int j = 0; j < 4; j++) acc[nt][j] = 0.f;

    uint2 b0[4], b1[4];
    #pragma unroll
    for (int t = 0; t < 4; t++) {
        b0[t] = v0 ? A0[t * 4 + c] : z2;
        b1[t] = v1 ? A1[t * 4 + c] : z2;
    }
    #pragma unroll
    for (int ch = 0; ch < 4; ch++) {
        uint2 n0[4], n1[4];
        #pragma unroll
        for (int t = 0; t < 4; t++) {
            n0[t] = (v0 && ch < 3) ? A0[(ch + 1) * 16 + t * 4 + c] : z2;
            n1[t] = (v1 && ch < 3) ? A1[(ch + 1) * 16 + t * 4 + c] : z2;
        }
        #pragma unroll
        for (int t = 0; t < 4; t++) {
            int wnd = ch * 4 + t;
            float4 fa0 = h4_to_f4(b0[t]);
            float4 fa1 = h4_to_f4(b1[t]);
            uint32_t a00 = f2tf32(fa0.x), a01 = f2tf32(fa0.y), a02 = f2tf32(fa0.z), a03 = f2tf32(fa0.w);
            uint32_t a10 = f2tf32(fa1.x), a11 = f2tf32(fa1.y), a12 = f2tf32(fa1.z), a13 = f2tf32(fa1.w);
            const uint32_t* bP = sB + (wnd * 8 + 2 * c) * S2P + 2 * g;
            #pragma unroll
            for (int nt = 0; nt < 7; nt++) {
                uint2 bb = *(const uint2*)(bP + 16 * nt);
                mma_tf32(acc[nt], a00, a10, a01, a11, bb.x, bb.y);
            }
            const uint32_t* bQ = bP + S2P;
            #pragma unroll
            for (int nt = 0; nt < 7; nt++) {
                uint2 bb = *(const uint2*)(bQ + 16 * nt);
                mma_tf32(acc[nt], a02, a12, a03, a13, bb.x, bb.y);
            }
        }
        #pragma unroll
        for (int t = 0; t < 4; t++) { b0[t] = n0[t]; b1[t] = n1[t]; }
    }
    #pragma unroll
    for (int nt = 0; nt < 7; nt++) {
        int col = nt * 8 + 2 * c;
        if (col < 48) {
            if (v0) ((__half2*)g_h2ph)[(size_t)row0 * 24 + nt * 4 + c] = __floats2half2_rn(acc[nt][0], acc[nt][1]);
            if (v1) ((__half2*)g_h2ph)[(size_t)row1 * 24 + nt * 4 + c] = __floats2half2_rn(acc[nt][2], acc[nt][3]);
        } else if (col == 48) {
            if (v0) { g_el2[row0] = acc[nt][0]; g_er2[row0] = acc[nt][1]; }
            if (v1) { g_el2[row1] = acc[nt][2]; g_er2[row1] = acc[nt][3]; }
        }
    }
}

// ---------------- layer-2 aggregation (scalar fp16 gathers) + log_softmax ----------------
__global__ void __launch_bounds__(256) k_agg2(const float* __restrict__ b2, float* __restrict__ out) {
    int wid = threadIdx.x >> 5, lane = threadIdx.x & 31;
    int i = blockIdx.x * 8 + wid;
    float el = g_el2[i];
    float accx = 0.f, accy = 0.f, denp = 0.f;
    int beg = g_rowptr[i], end = g_rowptr[i + 1];
    const __half2* __restrict__ h2p2 = (const __half2*)g_h2ph;
    for (int base = beg; base < end; base += 32) {
        int nb = min(32, end - base);
        int dstl = (lane < nb) ? g_csr_dst[base + lane] : 0;
        float wl_ = 0.f;
        if (lane < nb) {
            float a = el + g_er2[dstl];
            float lr = a > 0.f ? a : 0.2f * a;
            wl_ = __expf(lr);
            denp += wl_;
        }
        for (int j = 0; j < nb; j += 8) {
            int dd[8];
            float wv[8];
            #pragma unroll
            for (int u = 0; u < 8; u++) {
                dd[u] = __shfl_sync(0xffffffffu, dstl, j + u);
                wv[u] = __shfl_sync(0xffffffffu, wl_, j + u);
            }
            if (lane < 24) {
                __half2 hh[8];
                #pragma unroll
                for (int u = 0; u < 8; u++)
                    hh[u] = h2p2[dd[u] * 24 + lane];
                #pragma unroll
                for (int u = 0; u < 8; u++) {
                    accx = fmaf(wv[u], __low2float(hh[u]), accx);
                    accy = fmaf(wv[u], __high2float(hh[u]), accy);
                }
            }
        }
    }
    float den = denp;
    #pragma unroll
    for (int d = 16; d > 0; d >>= 1) den += __shfl_xor_sync(0xffffffffu, den, d);
    float rden = __fdividef(1.f, fmaxf(den, 1e-12f));
    float vx = -3.0e38f, vy = -3.0e38f;
    if (lane < 24) {
        vx = fmaf(accx, rden, b2[2 * lane]);
        vy = (2 * lane + 1 < NC) ? fmaf(accy, rden, b2[2 * lane + 1]) : -3.0e38f;
    }
    float m = fmaxf(vx, vy);
    #pragma unroll
    for (int d = 16; d > 0; d >>= 1) m = fmaxf(m, __shfl_xor_sync(0xffffffffu, m, d));
    float s = 0.f;
    if (lane < 24) {
        s = __expf(vx - m);
        if (2 * lane + 1 < NC) s += __expf(vy - m);
    }
    #pragma unroll
    for (int d = 16; d > 0; d >>= 1) s += __shfl_xor_sync(0xffffffffu, s, d);
    float ls = logf(s);
    if (lane < 24) {
        out[(size_t)i * NC + 2 * lane] = vx - m - ls;
        if (2 * lane + 1 < NC) out[(size_t)i * NC + 2 * lane + 1] = vy - m - ls;
    }
}

// ---------------- launch (6 kernels; #4 = k_agg1 -> profiled) ----------------
extern "C" void kernel_launch(void* const* d_in, const int* in_sizes, int n_in,
                              void* d_out, int out_size) {
    const float* x    = (const float*)d_in[0];
    const int*   esrc = (const int*)  d_in[1];
    const int*   edst = (const int*)  d_in[2];
    const float* W1   = (const float*)d_in[3];
    const float* Wl1  = (const float*)d_in[4];
    const float* Wr1  = (const float*)d_in[5];
    const float* b1   = (const float*)d_in[6];
    const float* W2   = (const float*)d_in[7];
    const float* Wl2  = (const float*)d_in[8];
    const float* Wr2  = (const float*)d_in[9];
    const float* b2   = (const float*)d_in[10];
    float* out = (float*)d_out;

    const int smem1 = 128 * S1P * 4;   // 51.2 KB
    const int smem2 = 128 * S2P * 4;   // 59.4 KB
    cudaFuncSetAttribute(k_gemm1, cudaFuncAttributeMaxDynamicSharedMemorySize, smem1);
    cudaFuncSetAttribute(k_gemm2, cudaFuncAttributeMaxDynamicSharedMemorySize, smem2);

    k_zero<<<(Nn + 1 + 255) / 256, 256>>>();
    k_gemm1<<<(Nn + 127) / 128, 256, smem1>>>(x, W1, Wl1, Wr1, esrc);
    k_scan_scatter<<<49, 1024>>>(esrc, edst);
    k_agg1<<<Nn / 8, 256>>>(b1);                    // #4 <- profiled
    k_gemm2<<<(Nn + 127) / 128, 256, smem2>>>(W2, Wl2, Wr2);
    k_agg2<<<Nn / 8, 256>>>(b2, out);
}